// round 14
// baseline (speedup 1.0000x reference)
#include <cuda_runtime.h>

#define B_   32
#define N_   512
#define M_   512
#define D_   64
#define BIGF 1e10f
#define INV_LN2 1.4426950408889634f
#define LN2     0.6931471805599453f
#define BIGQ (BIGF * INV_LN2)

// Feed: g_F[((b*8+w)*2+p)*FSTRIDE + s*32 + l], row = 64w+2l+p, s = col + l.
#define FSTRIDE (544 * 32)
__device__ float  g_F[(size_t)B_ * 8 * 2 * FSTRIDE];
__device__ float2 g_bnd[B_ * 256];     // row-256 boundary ring (col j -> slot j&255)
__device__ unsigned g_wf[B_];          // lower-block completed rounds
__device__ unsigned g_rf[B_];          // upper-block completed rounds

__device__ __forceinline__ float ex2f(float x) {
    float y; asm("ex2.approx.ftz.f32 %0, %1;" : "=f"(y) : "f"(x)); return y;
}
__device__ __forceinline__ float lg2f(float x) {
    float y; asm("lg2.approx.ftz.f32 %0, %1;" : "=f"(y) : "f"(x)); return y;
}
__device__ __forceinline__ unsigned ld_acq(const unsigned* p) {
    unsigned v; asm volatile("ld.acquire.gpu.global.u32 %0, [%1];" : "=r"(v) : "l"(p) : "memory"); return v;
}
__device__ __forceinline__ void red_rel(unsigned* p) {
    asm volatile("red.release.gpu.global.add.u32 [%0], 1;" :: "l"(p) : "memory");
}

#define TS  64
#define SP  68
#define TSP 66

__global__ __launch_bounds__(256) void dist_kernel(const float* __restrict__ x,
                                                   const float* __restrict__ y) {
    __shared__ float Xs[D_ * SP];
    __shared__ float Ys[D_ * SP];
    __shared__ float xn[TS], yn[TS];

    const int b  = blockIdx.z;
    const int i0 = blockIdx.y * TS;
    const int j0 = blockIdx.x * TS;
    const float* xb = x + ((size_t)b * N_ + i0) * D_;
    const float* yb = y + ((size_t)b * M_ + j0) * D_;
    const int tid = threadIdx.x;

    if (tid == 0 && blockIdx.x == 0 && blockIdx.y == 0) {
        g_wf[b] = 0; g_rf[b] = 0;      // per-launch flag reset (graph-replay safe)
    }

#pragma unroll
    for (int it = 0; it < 4; ++it) {
        int f = tid + it * 256, row = f & 63, c4 = f >> 6;
        float4 vx = *(const float4*)(xb + row * D_ + c4 * 4);
        float4 vy = *(const float4*)(yb + row * D_ + c4 * 4);
        Xs[(c4*4+0)*SP+row] = vx.x; Xs[(c4*4+1)*SP+row] = vx.y;
        Xs[(c4*4+2)*SP+row] = vx.z; Xs[(c4*4+3)*SP+row] = vx.w;
        Ys[(c4*4+0)*SP+row] = vy.x; Ys[(c4*4+1)*SP+row] = vy.y;
        Ys[(c4*4+2)*SP+row] = vy.z; Ys[(c4*4+3)*SP+row] = vy.w;
    }
    __syncthreads();

    if (tid < 64) {
        float s = 0.f;
#pragma unroll
        for (int k = 0; k < D_; ++k) { float v = Xs[k*SP+tid]; s = fmaf(v, v, s); }
        xn[tid] = s;
    } else if (tid < 128) {
        int r = tid - 64; float s = 0.f;
#pragma unroll
        for (int k = 0; k < D_; ++k) { float v = Ys[k*SP+r]; s = fmaf(v, v, s); }
        yn[r] = s;
    }
    __syncthreads();

    const int tx = tid & 15, ty = tid >> 4;
    const int ia = ty * 4, ja = tx * 4;
    float acc[4][4] = {};
#pragma unroll
    for (int k = 0; k < D_; ++k) {
        float4 a  = *(const float4*)&Xs[k*SP+ia];
        float4 bb = *(const float4*)&Ys[k*SP+ja];
        float av[4] = {a.x,a.y,a.z,a.w}, bv[4] = {bb.x,bb.y,bb.z,bb.w};
#pragma unroll
        for (int r = 0; r < 4; ++r)
#pragma unroll
            for (int c = 0; c < 4; ++c)
                acc[r][c] = fmaf(av[r], bv[c], acc[r][c]);
    }
    float x2v[4], y2v[4];
#pragma unroll
    for (int r = 0; r < 4; ++r) x2v[r] = xn[ia+r];
#pragma unroll
    for (int c = 0; c < 4; ++c) y2v[c] = yn[ja+c];

    __syncthreads();
    float* Ts = Xs;
#pragma unroll
    for (int r = 0; r < 4; ++r)
#pragma unroll
        for (int c = 0; c < 4; ++c)
            Ts[(ia+r)*TSP + ja+c] = fmaf(-2.f, acc[r][c], x2v[r]+y2v[c]) * INV_LN2;
    __syncthreads();

    const int wD = blockIdx.y, wd = tid >> 5, l = tid & 31;
    float* F0 = g_F + ((size_t)(b * 8 + wD) * 2) * FSTRIDE;
#pragma unroll
    for (int p = 0; p < 2; ++p) {
        float* Fp = F0 + p * FSTRIDE;
#pragma unroll
        for (int it = 0; it < 16; ++it) {
            int s_rel = it * 8 + wd;
            int lv = s_rel - l;
            if (lv >= 0 && lv < 64)
                Fp[(j0 + s_rel) * 32 + l] = Ts[(2*l+p)*TSP + lv];
        }
    }
}

// ---------------------------------------------------------------------------
// soft-DTW: 2 blocks per batch (rows 1-256 / 257-512), 4 warps each.
// Same 31-round pipeline as the 8-warp version (upper warp w == global 4+w).
// Inner body: 3-exp deferred-log softmin. Row-256 boundary crosses blocks via
// g_bnd + acquire/release round counters.
// ---------------------------------------------------------------------------
#define NR2 31

template <int MODE, int COFF>   // MODE: 0 head, 1 clean, 2 tail
__device__ __forceinline__ void half16(
    int rbase, int l, bool pR, bool pW, bool w0l0,
    const float2* __restrict__ ringrd, float2* wbase, unsigned wmask,
    const float* __restrict__ dA, const float* __restrict__ dB,
    float& qT, float& sT, float& qB, float& sB, float& hq, float& hs)
{
#pragma unroll
    for (int cc = 0; cc < 16; ++cc) {
        const int c = COFF + cc;

        float sq = __shfl_up_sync(0xffffffffu, qB, 1);
        float ss = __shfl_up_sync(0xffffffffu, sB, 1);
        if (pR) { float2 rv = ringrd[(rbase + cc) & 127]; sq = rv.x; ss = rv.y; }

        float q0 = hq, s0 = hs;
        if (MODE == 0 && c == 0 && w0l0) { q0 = 0.f; s0 = 1.f; }   // R[0][0]

        // top cell: r0=(q0,s0), r1=(sq,ss), r2=(qT,sT)
        float m  = fminf(fminf(q0, qT), sq);
        float e0 = ex2f(m - q0), e1 = ex2f(m - sq), e2 = ex2f(m - qT);
        float snT = fmaf(s0, e0, fmaf(ss, e1, sT * e2));
        float qnT = dA[cc] + m;

        // bottom cell: r0=(qT,sT) old top, r1=(qnT,snT), r2=(qB,sB)
        float mb = fminf(fminf(qT, qB), qnT);
        float f0 = ex2f(mb - qT), f1 = ex2f(mb - qnT), f2 = ex2f(mb - qB);
        float snB = fmaf(sT, f0, fmaf(snT, f1, sB * f2));
        float qnB = dB[cc] + mb;

        bool actc = true;
        if (MODE == 0) actc = (c >= l);
        if (MODE == 2) actc = (c < l);
        if (actc) { qT = qnT; sT = snT; qB = qnB; sB = snB; }
        hq = sq; hs = ss;

        bool wr = pW && (MODE == 1 || actc);
        if (wr) wbase[(unsigned)(rbase + cc - 31) & wmask] = make_float2(qB, sB);
    }
}

__global__ void __launch_bounds__(128, 1) dtw_kernel(float* __restrict__ out) {
    __shared__ float2 ring[5][128];       // row 4: const BIGQ (lower) / staged (upper)

    const int blk = blockIdx.x, b = blk >> 1, hi = blk & 1;
    const int tid = threadIdx.x, wl = tid >> 5, l = tid & 31;
    const int wg = hi * 4 + wl;           // global warp id 0..7

    if (tid < 128) ring[4][tid] = make_float2(BIGQ, 1.f);

    const bool pR   = (l == 0);
    const bool pW   = (l == 31);
    const bool w0l0 = (wg == 0) && (l == 0);
    const bool stage = (hi == 1) && (wl == 0);   // polls g_wf, stages g_bnd -> ring[4]
    const bool gwrit = (hi == 0) && (wl == 3);   // writes boundary to g_bnd

    const float2* ringrd = (wl == 0) ? ring[4] : ring[wl - 1];
    float2* bnd = g_bnd + b * 256;
    float2* wbase  = gwrit ? bnd : ring[wl];
    unsigned wmask = gwrit ? 255u : 127u;

    const float* FT = g_F + ((size_t)(b * 8 + wg) * 2) * FSTRIDE + l;
    const float* FB = FT + FSTRIDE;

    float qT = BIGQ, sT = 1.f, qB = BIGQ, sB = 1.f;
    float hq = BIGQ, hs = 1.f;
    float a0[16], b0[16], a1[16], b1[16];

    if (wg == 0) {
#pragma unroll
        for (int c = 0; c < 16; ++c) { a0[c] = __ldg(FT + c*32); b0[c] = __ldg(FB + c*32); }
    }
    __syncthreads();

    for (int r = 0; r < NR2; ++r) {
        const int rho = r - 2 * wg;

        if (stage && rho >= 0 && rho <= 16) {
            while ((int)ld_acq(&g_wf[b]) < r) {}          // lower finished round r-1
            float2 v = bnd[(32 * rho + 1 + l) & 255];
            ring[4][(32 * rho + 1 + l) & 127] = v;
            __syncwarp();
        }
        if (gwrit && l == 31 && rho >= 0 && rho <= 16) {
            while ((int)ld_acq(&g_rf[b]) < r - 5) {}      // ring-slot backpressure
        }

        const bool act_nxt = (r + 1 >= 2 * wg) && (r + 1 <= 2 * wg + 16);
        if (act_nxt) {
            const int sb = (rho + 1) * 32;
            (void)sb;
        }

        if (rho >= 0 && rho <= 16) {
            const int sb = rho * 32;
#pragma unroll
            for (int c = 0; c < 16; ++c) {                 // prefetch this round's half1
                a1[c] = __ldg(FT + (sb + 16 + c)*32);
                b1[c] = __ldg(FB + (sb + 16 + c)*32);
            }
            const int rbase = sb + 1;
            if (rho == 0)
                half16<0, 0>(rbase, l, pR, pW, w0l0, ringrd, wbase, wmask, a0, b0, qT, sT, qB, sB, hq, hs);
            else if (rho < 16)
                half16<1, 0>(rbase, l, pR, pW, w0l0, ringrd, wbase, wmask, a0, b0, qT, sT, qB, sB, hq, hs);
            else
                half16<2, 0>(rbase, l, pR, pW, w0l0, ringrd, wbase, wmask, a0, b0, qT, sT, qB, sB, hq, hs);

            if (rho < 16) {                                // prefetch next round's half0
#pragma unroll
                for (int c = 0; c < 16; ++c) {
                    a0[c] = __ldg(FT + (sb + 32 + c)*32);
                    b0[c] = __ldg(FB + (sb + 32 + c)*32);
                }
            }
            if (rho == 0)
                half16<0, 16>(rbase + 16, l, pR, pW, w0l0, ringrd, wbase, wmask, a1, b1, qT, sT, qB, sB, hq, hs);
            else if (rho < 16)
                half16<1, 16>(rbase + 16, l, pR, pW, w0l0, ringrd, wbase, wmask, a1, b1, qT, sT, qB, sB, hq, hs);
            else
                half16<2, 16>(rbase + 16, l, pR, pW, w0l0, ringrd, wbase, wmask, a1, b1, qT, sT, qB, sB, hq, hs);

            qT -= lg2f(sT); sT = 1.f;                      // value-preserving renorm
            qB -= lg2f(sB); sB = 1.f;
        } else if (rho == -1) {                            // prime my first half0
#pragma unroll
            for (int c = 0; c < 16; ++c) { a0[c] = __ldg(FT + c*32); b0[c] = __ldg(FB + c*32); }
        }

        if (gwrit && l == 31) red_rel(&g_wf[b]);           // every round
        if (stage && l == 0)  red_rel(&g_rf[b]);           // every round
        __syncthreads();
    }

    if (wg == 7 && l == 31)
        out[b] = (qB - lg2f(sB)) * LN2;                    // R[512][512]
}

extern "C" void kernel_launch(void* const* d_in, const int* in_sizes, int n_in,
                              void* d_out, int out_size) {
    const float* x = (const float*)d_in[0];
    const float* y = (const float*)d_in[1];
    float* out = (float*)d_out;

    dim3 dgrid(M_ / TS, N_ / TS, B_);
    dist_kernel<<<dgrid, 256>>>(x, y);
    dtw_kernel<<<2 * B_, 128>>>(out);
}

// round 15
// speedup vs baseline: 1.1605x; 1.1605x over previous
#include <cuda_runtime.h>

#define B_   32
#define N_   512
#define M_   512
#define D_   64
#define BIGF 1e10f
#define INV_LN2 1.4426950408889634f
#define LN2     0.6931471805599453f
#define BIGQ (BIGF * INV_LN2)

// Feed: g_F[((b*8+w)*2+p)*FSTRIDE + s*32 + l], row = 64w+2l+p, s = col + l.
#define FSTRIDE (544 * 32)
__device__ float g_F[(size_t)B_ * 8 * 2 * FSTRIDE];

__device__ __forceinline__ float ex2f(float x) {
    float y; asm("ex2.approx.ftz.f32 %0, %1;" : "=f"(y) : "f"(x)); return y;
}
__device__ __forceinline__ float lg2f(float x) {
    float y; asm("lg2.approx.ftz.f32 %0, %1;" : "=f"(y) : "f"(x)); return y;
}

#define TS  64
#define SP  68
#define TSP 66

__global__ __launch_bounds__(256) void dist_kernel(const float* __restrict__ x,
                                                   const float* __restrict__ y) {
    __shared__ float Xs[D_ * SP];
    __shared__ float Ys[D_ * SP];
    __shared__ float xn[TS], yn[TS];

    const int b  = blockIdx.z;
    const int i0 = blockIdx.y * TS;
    const int j0 = blockIdx.x * TS;
    const float* xb = x + ((size_t)b * N_ + i0) * D_;
    const float* yb = y + ((size_t)b * M_ + j0) * D_;
    const int tid = threadIdx.x;

#pragma unroll
    for (int it = 0; it < 4; ++it) {
        int f = tid + it * 256, row = f & 63, c4 = f >> 6;
        float4 vx = *(const float4*)(xb + row * D_ + c4 * 4);
        float4 vy = *(const float4*)(yb + row * D_ + c4 * 4);
        Xs[(c4*4+0)*SP+row] = vx.x; Xs[(c4*4+1)*SP+row] = vx.y;
        Xs[(c4*4+2)*SP+row] = vx.z; Xs[(c4*4+3)*SP+row] = vx.w;
        Ys[(c4*4+0)*SP+row] = vy.x; Ys[(c4*4+1)*SP+row] = vy.y;
        Ys[(c4*4+2)*SP+row] = vy.z; Ys[(c4*4+3)*SP+row] = vy.w;
    }
    __syncthreads();

    if (tid < 64) {
        float s = 0.f;
#pragma unroll
        for (int k = 0; k < D_; ++k) { float v = Xs[k*SP+tid]; s = fmaf(v, v, s); }
        xn[tid] = s;
    } else if (tid < 128) {
        int r = tid - 64; float s = 0.f;
#pragma unroll
        for (int k = 0; k < D_; ++k) { float v = Ys[k*SP+r]; s = fmaf(v, v, s); }
        yn[r] = s;
    }
    __syncthreads();

    const int tx = tid & 15, ty = tid >> 4;
    const int ia = ty * 4, ja = tx * 4;
    float acc[4][4] = {};
#pragma unroll
    for (int k = 0; k < D_; ++k) {
        float4 a  = *(const float4*)&Xs[k*SP+ia];
        float4 bb = *(const float4*)&Ys[k*SP+ja];
        float av[4] = {a.x,a.y,a.z,a.w}, bv[4] = {bb.x,bb.y,bb.z,bb.w};
#pragma unroll
        for (int r = 0; r < 4; ++r)
#pragma unroll
            for (int c = 0; c < 4; ++c)
                acc[r][c] = fmaf(av[r], bv[c], acc[r][c]);
    }
    float x2v[4], y2v[4];
#pragma unroll
    for (int r = 0; r < 4; ++r) x2v[r] = xn[ia+r];
#pragma unroll
    for (int c = 0; c < 4; ++c) y2v[c] = yn[ja+c];

    __syncthreads();
    float* Ts = Xs;
#pragma unroll
    for (int r = 0; r < 4; ++r)
#pragma unroll
        for (int c = 0; c < 4; ++c)
            Ts[(ia+r)*TSP + ja+c] = fmaf(-2.f, acc[r][c], x2v[r]+y2v[c]) * INV_LN2;
    __syncthreads();

    // Drain: (row=2l+p, col=lv) -> g_F[(b*8+wD)*2+p][(j0+s_rel)*32+l], s_rel = lv+l.
    const int wD = blockIdx.y, wd = tid >> 5, l = tid & 31;
    float* F0 = g_F + ((size_t)(b * 8 + wD) * 2) * FSTRIDE;
#pragma unroll
    for (int p = 0; p < 2; ++p) {
        float* Fp = F0 + p * FSTRIDE;
#pragma unroll
        for (int it = 0; it < 16; ++it) {
            int s_rel = it * 8 + wd;
            int lv = s_rel - l;
            if (lv >= 0 && lv < 64)
                Fp[(j0 + s_rel) * 32 + l] = Ts[(2*l+p)*TSP + lv];
        }
    }
}

// ---------------------------------------------------------------------------
// soft-DTW: 8 warps/batch; lane l of warp w owns rows 64w+2l+1, 64w+2l+2.
// Deferred-log (q,s) state, 3-exp softmin (lean issue count), 31 rounds x 32
// steps, warp lag 2 rounds, smem boundary ring. (R12 shell + R13 body.)
// ---------------------------------------------------------------------------
#define NR2 31

template <int MODE, int COFF>   // MODE: 0 head, 1 clean, 2 tail
__device__ __forceinline__ void half16(
    int rbase, int l, bool pR, bool pW, bool w0l0,
    const float2* __restrict__ ringrd, float2* __restrict__ ringwr,
    const float* __restrict__ dA, const float* __restrict__ dB,
    float& qT, float& sT, float& qB, float& sB, float& hq, float& hs)
{
#pragma unroll
    for (int cc = 0; cc < 16; ++cc) {
        const int c = COFF + cc;

        float sq = __shfl_up_sync(0xffffffffu, qB, 1);
        float ss = __shfl_up_sync(0xffffffffu, sB, 1);
        if (pR) { float2 rv = ringrd[(rbase + cc) & 127]; sq = rv.x; ss = rv.y; }

        float q0 = hq, s0 = hs;
        if (MODE == 0 && c == 0 && w0l0) { q0 = 0.f; s0 = 1.f; }   // R[0][0]

        // top cell: r0=(q0,s0), r1=(sq,ss), r2=(qT,sT)
        float mA = fminf(q0, qT);
        float m  = fminf(mA, sq);
        float e0 = ex2f(m - q0), e1 = ex2f(m - sq), e2 = ex2f(m - qT);
        float snT = fmaf(s0, e0, fmaf(ss, e1, sT * e2));
        float qnT = dA[cc] + m;

        // bottom cell: r0 = old top (qT,sT), r1=(qnT,snT), r2=(qB,sB)
        float mB0 = fminf(qT, qB);                 // off the qnT chain
        float mb  = fminf(mB0, qnT);
        float f0 = ex2f(mb - qT), f1 = ex2f(mb - qnT), f2 = ex2f(mb - qB);
        float snB = fmaf(sT, f0, fmaf(snT, f1, sB * f2));
        float qnB = dB[cc] + mb;

        bool actc = true;
        if (MODE == 0) actc = (c >= l);
        if (MODE == 2) actc = (c < l);
        if (actc) { qT = qnT; sT = snT; qB = qnB; sB = snB; }
        hq = sq; hs = ss;

        bool wr = pW && (MODE == 1 || actc);
        if (wr) ringwr[(rbase + cc - 31) & 127] = make_float2(qB, sB);
    }
}

__global__ void __launch_bounds__(256, 1) dtw_kernel(float* __restrict__ out) {
    __shared__ float2 ring[9][128];          // row 8 = constant BIGQ row

    const int b   = blockIdx.x;
    const int tid = threadIdx.x;
    const int w   = tid >> 5;
    const int l   = tid & 31;

    if (tid < 128) ring[8][tid] = make_float2(BIGQ, 1.f);

    const bool pR   = (l == 0);
    const bool pW   = (l == 31);
    const bool w0l0 = (w == 0) && (l == 0);
    const float2* ringrd = (w == 0) ? ring[8] : ring[w - 1];
    float2*       ringwr = ring[w];

    const float* FT = g_F + ((size_t)(b * 8 + w) * 2) * FSTRIDE + l;
    const float* FB = FT + FSTRIDE;

    float qT = BIGQ, sT = 1.f, qB = BIGQ, sB = 1.f;
    float hq = BIGQ, hs = 1.f;
    float a0[16], b0[16], a1[16], b1[16];

    if (w == 0) {
#pragma unroll
        for (int c = 0; c < 16; ++c) { a0[c] = __ldg(FT + c*32); b0[c] = __ldg(FB + c*32); }
    }
    __syncthreads();

    for (int r = 0; r < NR2; ++r) {
        const int rho = r - 2 * w;
        if (rho >= 0 && rho <= 16) {
            const int sb = rho * 32;
            // prefetch this round's half1
#pragma unroll
            for (int c = 0; c < 16; ++c) {
                a1[c] = __ldg(FT + (sb + 16 + c)*32);
                b1[c] = __ldg(FB + (sb + 16 + c)*32);
            }
            const int rbase = sb + 1;
            if (rho == 0)
                half16<0, 0>(rbase, l, pR, pW, w0l0, ringrd, ringwr, a0, b0, qT, sT, qB, sB, hq, hs);
            else if (rho < 16)
                half16<1, 0>(rbase, l, pR, pW, w0l0, ringrd, ringwr, a0, b0, qT, sT, qB, sB, hq, hs);
            else
                half16<2, 0>(rbase, l, pR, pW, w0l0, ringrd, ringwr, a0, b0, qT, sT, qB, sB, hq, hs);

            if (rho < 16) {   // prefetch next round's half0
#pragma unroll
                for (int c = 0; c < 16; ++c) {
                    a0[c] = __ldg(FT + (sb + 32 + c)*32);
                    b0[c] = __ldg(FB + (sb + 32 + c)*32);
                }
            }
            if (rho == 0)
                half16<0, 16>(rbase + 16, l, pR, pW, w0l0, ringrd, ringwr, a1, b1, qT, sT, qB, sB, hq, hs);
            else if (rho < 16)
                half16<1, 16>(rbase + 16, l, pR, pW, w0l0, ringrd, ringwr, a1, b1, qT, sT, qB, sB, hq, hs);
            else
                half16<2, 16>(rbase + 16, l, pR, pW, w0l0, ringrd, ringwr, a1, b1, qT, sT, qB, sB, hq, hs);

            qT -= lg2f(sT); sT = 1.f;        // value-preserving renorm
            qB -= lg2f(sB); sB = 1.f;
        } else if (rho == -1) {              // prime my first half0
#pragma unroll
            for (int c = 0; c < 16; ++c) { a0[c] = __ldg(FT + c*32); b0[c] = __ldg(FB + c*32); }
        }
        __syncthreads();
    }

    if (w == 7 && l == 31)
        out[b] = (qB - lg2f(sB)) * LN2;      // R[512][512]
}

extern "C" void kernel_launch(void* const* d_in, const int* in_sizes, int n_in,
                              void* d_out, int out_size) {
    const float* x = (const float*)d_in[0];
    const float* y = (const float*)d_in[1];
    float* out = (float*)d_out;

    dim3 dgrid(M_ / TS, N_ / TS, B_);
    dist_kernel<<<dgrid, 256>>>(x, y);
    dtw_kernel<<<B_, 256>>>(out);
}